// round 2
// baseline (speedup 1.0000x reference)
#include <cuda_runtime.h>
#include <cstdint>

#define DIM 1024

// Scratch for the computed mask (allocation-free per harness rules).
__device__ __align__(16) float g_mask[DIM];

// Kernel 1: mask = DIM * softmax(mask_param) * _mask
// Single block, 1024 threads. Writes to g_mask (for kernel 2) and to the
// tail of d_out (the second tuple element of the reference output).
__global__ void mask_softmax_kernel(const float* __restrict__ mask_param,
                                    const float* __restrict__ mask_fixed,
                                    float* __restrict__ out_mask) {
    __shared__ float red[DIM];
    const int t = threadIdx.x;
    const float v = mask_param[t];

    // max-reduce
    red[t] = v;
    __syncthreads();
    #pragma unroll
    for (int s = DIM / 2; s > 0; s >>= 1) {
        if (t < s) red[t] = fmaxf(red[t], red[t + s]);
        __syncthreads();
    }
    const float mx = red[0];
    __syncthreads();

    // sum-reduce of exp
    const float e = __expf(v - mx);
    red[t] = e;
    __syncthreads();
    #pragma unroll
    for (int s = DIM / 2; s > 0; s >>= 1) {
        if (t < s) red[t] += red[t + s];
        __syncthreads();
    }
    const float inv_sum = 1.0f / red[0];

    const float m = (float)DIM * e * inv_sum * mask_fixed[t];
    g_mask[t] = m;
    out_mask[t] = m;
}

// Kernel 2: xm = x * mask (channel broadcast), float4-vectorized.
// blockDim == 256 == DIM/4, so the per-thread channel float4 index is
// exactly threadIdx.x (global float4 index mod 256 == threadIdx.x).
__global__ void __launch_bounds__(256) mask_mul_kernel(
        const float4* __restrict__ x,
        float4* __restrict__ out,
        long long n4) {
    const float4 m = reinterpret_cast<const float4*>(g_mask)[threadIdx.x];
    const long long i = (long long)blockIdx.x * 256 + threadIdx.x;
    if (i < n4) {
        float4 v = x[i];
        v.x *= m.x;
        v.y *= m.y;
        v.z *= m.z;
        v.w *= m.w;
        out[i] = v;
    }
}

extern "C" void kernel_launch(void* const* d_in, const int* in_sizes, int n_in,
                              void* d_out, int out_size) {
    const float* x          = (const float*)d_in[0];   // [8, 4096, 1024] f32
    const float* mask_param = (const float*)d_in[1];   // [1024] f32
    const float* mask_fixed = (const float*)d_in[2];   // [1024] f32

    float* out = (float*)d_out;
    const long long n  = (long long)in_sizes[0];       // 33,554,432
    const long long n4 = n / 4;                        // 8,388,608

    // Output layout: [xm (n floats)] [mask (1024 floats)]
    mask_softmax_kernel<<<1, DIM>>>(mask_param, mask_fixed, out + n);

    const int blocks = (int)((n4 + 255) / 256);        // 32768
    mask_mul_kernel<<<blocks, 256>>>(
        (const float4*)x, (float4*)out, n4);
}

// round 4
// speedup vs baseline: 1.0222x; 1.0222x over previous
#include <cuda_runtime.h>
#include <cstdint>

#define DIM 1024

// Scratch for the computed mask (allocation-free per harness rules).
__device__ __align__(16) float g_mask[DIM];

// Kernel 1: mask = DIM * softmax(mask_param) * _mask
// Single warp, 32 elements per thread, shuffle-only reductions (no barriers).
__global__ void mask_softmax_kernel(const float* __restrict__ mask_param,
                                    const float* __restrict__ mask_fixed,
                                    float* __restrict__ out_mask) {
    const int t = threadIdx.x;  // 0..31

    float v[32];
    #pragma unroll
    for (int i = 0; i < 32; i++)
        v[i] = mask_param[t + 32 * i];   // coalesced

    // max
    float mx = v[0];
    #pragma unroll
    for (int i = 1; i < 32; i++) mx = fmaxf(mx, v[i]);
    #pragma unroll
    for (int s = 16; s > 0; s >>= 1)
        mx = fmaxf(mx, __shfl_xor_sync(0xffffffffu, mx, s));

    // exp + sum
    float sum = 0.0f;
    #pragma unroll
    for (int i = 0; i < 32; i++) {
        v[i] = __expf(v[i] - mx);
        sum += v[i];
    }
    #pragma unroll
    for (int s = 16; s > 0; s >>= 1)
        sum += __shfl_xor_sync(0xffffffffu, sum, s);

    const float scale = (float)DIM / sum;
    #pragma unroll
    for (int i = 0; i < 32; i++) {
        const int idx = t + 32 * i;
        const float m = scale * v[i] * mask_fixed[idx];
        g_mask[idx] = m;
        out_mask[idx] = m;
    }
}

// Kernel 2: xm = x * mask (channel broadcast), float4-vectorized, unroll x4.
// Block handles 1024 consecutive float4s; thread t handles t, t+256, t+512,
// t+768 — all congruent to t mod 256, so one mask float4 serves all four.
// n4 = 8,388,608 = 8192 * 1024 exactly -> no tail handling.
__global__ void __launch_bounds__(256) mask_mul_kernel(
        const float4* __restrict__ x,
        float4* __restrict__ out) {
    const float4 m = reinterpret_cast<const float4*>(g_mask)[threadIdx.x];
    const long long base = (long long)blockIdx.x * 1024 + threadIdx.x;

    // Batch the four independent loads front-to-back for MLP.
    float4 a = x[base];
    float4 b = x[base + 256];
    float4 c = x[base + 512];
    float4 d = x[base + 768];

    a.x *= m.x; a.y *= m.y; a.z *= m.z; a.w *= m.w;
    b.x *= m.x; b.y *= m.y; b.z *= m.z; b.w *= m.w;
    c.x *= m.x; c.y *= m.y; c.z *= m.z; c.w *= m.w;
    d.x *= m.x; d.y *= m.y; d.z *= m.z; d.w *= m.w;

    out[base]       = a;
    out[base + 256] = b;
    out[base + 512] = c;
    out[base + 768] = d;
}

extern "C" void kernel_launch(void* const* d_in, const int* in_sizes, int n_in,
                              void* d_out, int out_size) {
    const float* x          = (const float*)d_in[0];   // [8, 4096, 1024] f32
    const float* mask_param = (const float*)d_in[1];   // [1024] f32
    const float* mask_fixed = (const float*)d_in[2];   // [1024] f32

    float* out = (float*)d_out;
    const long long n  = (long long)in_sizes[0];       // 33,554,432
    const long long n4 = n / 4;                        // 8,388,608

    // Output layout: [xm (n floats)] [mask (1024 floats)]
    mask_softmax_kernel<<<1, 32>>>(mask_param, mask_fixed, out + n);

    const int blocks = (int)(n4 / 1024);               // 8192
    mask_mul_kernel<<<blocks, 256>>>((const float4*)x, (float4*)out);
}

// round 6
// speedup vs baseline: 1.0674x; 1.0442x over previous
#include <cuda_runtime.h>
#include <cstdint>

#define DIM 1024

// Scratch for the computed mask (allocation-free per harness rules).
__device__ __align__(16) float g_mask[DIM];

// Kernel 1: mask = DIM * softmax(mask_param) * _mask
// Single warp, 32 elements per thread, shuffle-only reductions (no barriers).
// Signals dependent (PDL) kernels as soon as the mask is written.
__global__ void mask_softmax_kernel(const float* __restrict__ mask_param,
                                    const float* __restrict__ mask_fixed,
                                    float* __restrict__ out_mask) {
    const int t = threadIdx.x;  // 0..31

    float v[32];
    #pragma unroll
    for (int i = 0; i < 32; i++)
        v[i] = mask_param[t + 32 * i];   // coalesced

    // max
    float mx = v[0];
    #pragma unroll
    for (int i = 1; i < 32; i++) mx = fmaxf(mx, v[i]);
    #pragma unroll
    for (int s = 16; s > 0; s >>= 1)
        mx = fmaxf(mx, __shfl_xor_sync(0xffffffffu, mx, s));

    // exp + sum
    float sum = 0.0f;
    #pragma unroll
    for (int i = 0; i < 32; i++) {
        v[i] = __expf(v[i] - mx);
        sum += v[i];
    }
    #pragma unroll
    for (int s = 16; s > 0; s >>= 1)
        sum += __shfl_xor_sync(0xffffffffu, sum, s);

    const float scale = (float)DIM / sum;
    #pragma unroll
    for (int i = 0; i < 32; i++) {
        const int idx = t + 32 * i;
        const float m = scale * v[i] * mask_fixed[idx];
        g_mask[idx] = m;
        out_mask[idx] = m;
    }

    // Make g_mask visible and allow PDL dependents to proceed.
    __threadfence();
    asm volatile("griddepcontrol.launch_dependents;" ::: "memory");
}

// Kernel 2: xm = x * mask (channel broadcast), float4-vectorized, unroll x8.
// Launched with programmatic dependent launch: starts before kernel 1
// finishes, front-loads all 8 independent x loads (no mask dependency),
// then griddepcontrol.wait's before reading g_mask.
// Block handles 2048 consecutive float4s; thread t's offsets are all
// congruent to t mod 256, so one mask float4 serves all eight.
// n4 = 8,388,608 = 4096 * 2048 exactly -> no tail handling.
__global__ void __launch_bounds__(256) mask_mul_kernel(
        const float4* __restrict__ x,
        float4* __restrict__ out) {
    const long long base = (long long)blockIdx.x * 2048 + threadIdx.x;

    // Front-batched streaming loads (read-once: evict-first).
    float4 a = __ldcs(&x[base]);
    float4 b = __ldcs(&x[base +  256]);
    float4 c = __ldcs(&x[base +  512]);
    float4 d = __ldcs(&x[base +  768]);
    float4 e = __ldcs(&x[base + 1024]);
    float4 f = __ldcs(&x[base + 1280]);
    float4 g = __ldcs(&x[base + 1536]);
    float4 h = __ldcs(&x[base + 1792]);

    // Wait for the mask producer before touching g_mask.
    asm volatile("griddepcontrol.wait;" ::: "memory");
    const float4 m = reinterpret_cast<const float4*>(g_mask)[threadIdx.x];

    a.x *= m.x; a.y *= m.y; a.z *= m.z; a.w *= m.w;
    b.x *= m.x; b.y *= m.y; b.z *= m.z; b.w *= m.w;
    c.x *= m.x; c.y *= m.y; c.z *= m.z; c.w *= m.w;
    d.x *= m.x; d.y *= m.y; d.z *= m.z; d.w *= m.w;
    e.x *= m.x; e.y *= m.y; e.z *= m.z; e.w *= m.w;
    f.x *= m.x; f.y *= m.y; f.z *= m.z; f.w *= m.w;
    g.x *= m.x; g.y *= m.y; g.z *= m.z; g.w *= m.w;
    h.x *= m.x; h.y *= m.y; h.z *= m.z; h.w *= m.w;

    // Streaming stores (write-once: don't pollute L2).
    __stcs(&out[base],        a);
    __stcs(&out[base +  256], b);
    __stcs(&out[base +  512], c);
    __stcs(&out[base +  768], d);
    __stcs(&out[base + 1024], e);
    __stcs(&out[base + 1280], f);
    __stcs(&out[base + 1536], g);
    __stcs(&out[base + 1792], h);
}

extern "C" void kernel_launch(void* const* d_in, const int* in_sizes, int n_in,
                              void* d_out, int out_size) {
    const float* x          = (const float*)d_in[0];   // [8, 4096, 1024] f32
    const float* mask_param = (const float*)d_in[1];   // [1024] f32
    const float* mask_fixed = (const float*)d_in[2];   // [1024] f32

    float* out = (float*)d_out;
    const long long n  = (long long)in_sizes[0];       // 33,554,432
    const long long n4 = n / 4;                        // 8,388,608

    // Output layout: [xm (n floats)] [mask (1024 floats)]
    mask_softmax_kernel<<<1, 32>>>(mask_param, mask_fixed, out + n);

    // Mul kernel with programmatic dependent launch: overlaps with kernel 1.
    cudaLaunchConfig_t cfg = {};
    cfg.gridDim  = dim3((unsigned)(n4 / 2048));        // 4096
    cfg.blockDim = dim3(256);
    cfg.dynamicSmemBytes = 0;
    cfg.stream = 0;
    cudaLaunchAttribute attr[1];
    attr[0].id = cudaLaunchAttributeProgrammaticStreamSerialization;
    attr[0].val.programmaticStreamSerializationAllowed = 1;
    cfg.attrs = attr;
    cfg.numAttrs = 1;
    cudaLaunchKernelEx(&cfg, mask_mul_kernel, (const float4*)x, (float4*)out);
}

// round 7
// speedup vs baseline: 1.0788x; 1.0106x over previous
#include <cuda_runtime.h>
#include <cstdint>

#define DIM 1024

// Single fused kernel: every block redundantly computes the 1024-wide softmax
// mask (cheap: 4 exps/thread, hidden under the x-load latency), then applies
// it to its 1024-float4 slice of x. One launch, no inter-kernel dependency.
//
// Thread t multiplies float4 channel positions == t (mod 256), i.e. scalar
// channels [4t, 4t+3] — exactly the float4 of mask_param at index t.
__global__ void __launch_bounds__(256) fused_mask_mul_kernel(
        const float4* __restrict__ x,
        float4* __restrict__ out,
        const float4* __restrict__ mask_param4,
        const float4* __restrict__ mask_fixed4,
        float4* __restrict__ out_mask4) {
    const int t    = threadIdx.x;         // 0..255
    const int lane = t & 31;
    const int warp = t >> 5;              // 0..7

    // ---- Issue the 4 independent x loads first (latency we hide under) ----
    const long long base = (long long)blockIdx.x * 1024 + t;
    float4 a = x[base];
    float4 b = x[base + 256];
    float4 c = x[base + 512];
    float4 d = x[base + 768];

    // ---- Softmax over mask_param while loads are in flight ----
    const float4 p = mask_param4[t];      // channels 4t..4t+3 (L2-broadcast)

    __shared__ float sm[8];

    // block max
    float mx = fmaxf(fmaxf(p.x, p.y), fmaxf(p.z, p.w));
    #pragma unroll
    for (int s = 16; s > 0; s >>= 1)
        mx = fmaxf(mx, __shfl_xor_sync(0xffffffffu, mx, s));
    if (lane == 0) sm[warp] = mx;
    __syncthreads();
    #pragma unroll
    for (int w = 0; w < 8; w++) mx = fmaxf(mx, sm[w]);
    __syncthreads();                      // before smem reuse

    // exp + block sum
    float4 e;
    e.x = __expf(p.x - mx);
    e.y = __expf(p.y - mx);
    e.z = __expf(p.z - mx);
    e.w = __expf(p.w - mx);
    float sum = (e.x + e.y) + (e.z + e.w);
    #pragma unroll
    for (int s = 16; s > 0; s >>= 1)
        sum += __shfl_xor_sync(0xffffffffu, sum, s);
    if (lane == 0) sm[warp] = sum;
    __syncthreads();
    sum = 0.0f;
    #pragma unroll
    for (int w = 0; w < 8; w++) sum += sm[w];

    const float scale = (float)DIM / sum;
    const float4 f = mask_fixed4[t];
    float4 m;
    m.x = scale * e.x * f.x;
    m.y = scale * e.y * f.y;
    m.z = scale * e.z * f.z;
    m.w = scale * e.w * f.w;

    // One block emits the mask tuple element (tail of d_out).
    if (blockIdx.x == 0) out_mask4[t] = m;

    // ---- Apply mask and store ----
    a.x *= m.x; a.y *= m.y; a.z *= m.z; a.w *= m.w;
    b.x *= m.x; b.y *= m.y; b.z *= m.z; b.w *= m.w;
    c.x *= m.x; c.y *= m.y; c.z *= m.z; c.w *= m.w;
    d.x *= m.x; d.y *= m.y; d.z *= m.z; d.w *= m.w;

    out[base]       = a;
    out[base + 256] = b;
    out[base + 512] = c;
    out[base + 768] = d;
}

extern "C" void kernel_launch(void* const* d_in, const int* in_sizes, int n_in,
                              void* d_out, int out_size) {
    const float* x          = (const float*)d_in[0];   // [8, 4096, 1024] f32
    const float* mask_param = (const float*)d_in[1];   // [1024] f32
    const float* mask_fixed = (const float*)d_in[2];   // [1024] f32

    float* out = (float*)d_out;
    const long long n  = (long long)in_sizes[0];       // 33,554,432
    const long long n4 = n / 4;                        // 8,388,608

    const int blocks = (int)(n4 / 1024);               // 8192
    fused_mask_mul_kernel<<<blocks, 256>>>(
        (const float4*)x, (float4*)out,
        (const float4*)mask_param, (const float4*)mask_fixed,
        (float4*)(out + n));                           // mask tail
}